// round 16
// baseline (speedup 1.0000x reference)
#include <cuda_runtime.h>
#include <cstdint>

#define NNODE 16384
#define DFEAT 512
#define KTOP  16
#define BM 64
#define BN 256
#define BK 32
#define SPAD 65    // sim chunk stride (64 cols + 1)
#define TKPAD 17
#define STAGE_F (BK * BM + BK * BN)          // 10240 floats per pipeline stage
#define NCT (NNODE / BN)                     // 64 column tiles
#define NKI (DFEAT / BK)                     // 16 k-tiles per column tile
#define NKT (NCT * NKI)                      // 1024 total k-tiles

// Transposed normalized features: g_fnT[k][node]  (allocation-free scratch)
__device__ __align__(16) float g_fnT[(size_t)DFEAT * NNODE];

// ---- packed f32x2 helpers: each lane is an independent IEEE fp32 fmaf, so the
// per-element ascending-k chain is bit-identical to scalar fmaf ----
__device__ __forceinline__ unsigned long long f32x2_fma(
    unsigned long long a, unsigned long long b, unsigned long long c) {
    unsigned long long d;
    asm("fma.rn.f32x2 %0, %1, %2, %3;" : "=l"(d) : "l"(a), "l"(b), "l"(c));
    return d;
}
__device__ __forceinline__ unsigned long long f32x2_splat(float x) {
    unsigned long long d;
    asm("mov.b64 %0, {%1, %2};" : "=l"(d) : "f"(x), "f"(x));
    return d;
}
__device__ __forceinline__ void f32x2_unpack(unsigned long long v, float& lo, float& hi) {
    asm("mov.b64 {%0, %1}, %2;" : "=f"(lo), "=f"(hi) : "l"(v));
}
__device__ __forceinline__ void cp16(uint32_t saddr, const float* g) {
    asm volatile("cp.async.cg.shared.global [%0], [%1], 16;"
                 :: "r"(saddr), "l"(g) : "memory");
}

// ---------------------------------------------------------------------------
// Kernel 1 (FROZEN arithmetic — bit-matches reference, rel_err = 0):
// XLA:GPU row reduce: one warp/row, x2-vectorized, shfl_down tree,
// sqrt_rn + 1e-10, div_rn. Output stored TRANSPOSED (values unchanged).
// ---------------------------------------------------------------------------
__global__ void normalize_kernel(const float* __restrict__ f) {
    const int warp = threadIdx.x >> 5;
    const int lane = threadIdx.x & 31;
    const int row = blockIdx.x * 4 + warp;
    const float* src = f + (size_t)row * DFEAT;

    float acc = 0.f;
#pragma unroll
    for (int i = 0; i < 8; i++) {
        const float2 v = *(const float2*)(src + (((i << 5) + lane) << 1));
        acc = __fadd_rn(acc, __fmul_rn(v.x, v.x));
        acc = __fadd_rn(acc, __fmul_rn(v.y, v.y));
    }
#pragma unroll
    for (int off = 16; off > 0; off >>= 1)
        acc = __fadd_rn(acc, __shfl_down_sync(0xffffffffu, acc, off));

    float denom = __fadd_rn(__fsqrt_rn(acc), 1e-10f);
    denom = __shfl_sync(0xffffffffu, denom, 0);

#pragma unroll
    for (int j = 0; j < 16; j++) {
        int idx = lane + (j << 5);
        g_fnT[(size_t)idx * NNODE + row] = __fdiv_rn(src[idx], denom);
    }
}

// ---------------------------------------------------------------------------
// Kernel 2: fused sim-GEMM + per-row top-16.
// 64x256 CTA tile, 256 threads, 16x4 micro-tile (rows 16*ty..+15, cols
// 4*tx..+3), packed f32x2 FMA, cp.async 2-stage single-barrier pipeline.
// ---------------------------------------------------------------------------
extern __shared__ float smem[];

__device__ __forceinline__ void issue_tile(int t, int tid, int rowbase, uint32_t sbase) {
    const int colbase = (t >> 4) * BN;
    const int kk = (t & 15) * BK;
    const uint32_t abase = sbase + (uint32_t)((t & 1) * STAGE_F) * 4u;
    const uint32_t bbase = abase + (uint32_t)(BK * BM) * 4u;
#pragma unroll
    for (int j = 0; j < 2; j++) {               // A: 512 x 16B chunks
        int idx = tid + (j << 8);
        int k = idx >> 4, o = idx & 15;
        cp16(abase + (uint32_t)(k * BM + (o << 2)) * 4u,
             g_fnT + (size_t)(kk + k) * NNODE + rowbase + (o << 2));
    }
#pragma unroll
    for (int j = 0; j < 8; j++) {               // B: 2048 x 16B chunks
        int idx = tid + (j << 8);
        int k = idx >> 6, o = idx & 63;
        cp16(bbase + (uint32_t)(k * BN + (o << 2)) * 4u,
             g_fnT + (size_t)(kk + k) * NNODE + colbase + (o << 2));
    }
    asm volatile("cp.async.commit_group;" ::: "memory");
}

__global__ __launch_bounds__(256, 2) void simtopk_kernel(float* __restrict__ out) {
    float* tiles = smem;                        // 2 stages x (A + B)
    float* sim   = smem + 2 * STAGE_F;          // [BM][SPAD] 64-col chunk
    float* tv    = sim + BM * SPAD;             // [BM][TKPAD]
    int*   ti    = (int*)(tv + BM * TKPAD);

    const int tid = threadIdx.x;
    const int tx = tid & 63;                    // cols 4*tx .. 4*tx+3
    const int ty = tid >> 6;                    // rows 16*ty .. 16*ty+15 (warp-uniform)
    const int rowbase = blockIdx.x * BM;
    const uint32_t sbase = (uint32_t)__cvta_generic_to_shared(smem);

    for (int r = tid; r < BM; r += 256) {
#pragma unroll
        for (int p = 0; p < KTOP; p++) {
            tv[r * TKPAD + p] = -3.0e38f;
            ti[r * TKPAD + p] = 0;
        }
    }
    __syncthreads();   // topk init visible before first epilogue

    issue_tile(0, tid, rowbase, sbase);

    for (int ct = 0; ct < NCT; ct++) {
        unsigned long long acc2[8][4];          // 8 row-pairs x 4 cols
#pragma unroll
        for (int i = 0; i < 8; i++)
#pragma unroll
            for (int j = 0; j < 4; j++) acc2[i][j] = 0ull;

        for (int ki = 0; ki < NKI; ki++) {
            const int t = ct * NKI + ki;
            asm volatile("cp.async.wait_group 0;" ::: "memory");
            __syncthreads();
            // safe: all warps finished reading stage (t+1)&1 (= compute t-1)
            if (t + 1 < NKT) issue_tile(t + 1, tid, rowbase, sbase);

            const float* A = tiles + (t & 1) * STAGE_F;
            const float* B = A + BK * BM;
#pragma unroll
            for (int k = 0; k < BK; k++) {
                const ulonglong2 ap0 = *(const ulonglong2*)(A + k * BM + (ty << 4));
                const ulonglong2 ap1 = *(const ulonglong2*)(A + k * BM + (ty << 4) + 4);
                const ulonglong2 ap2 = *(const ulonglong2*)(A + k * BM + (ty << 4) + 8);
                const ulonglong2 ap3 = *(const ulonglong2*)(A + k * BM + (ty << 4) + 12);
                const float4 b = *(const float4*)(B + k * BN + (tx << 2));
                unsigned long long a2[8] = { ap0.x, ap0.y, ap1.x, ap1.y,
                                             ap2.x, ap2.y, ap3.x, ap3.y };
                unsigned long long sb[4] = {
                    f32x2_splat(b.x), f32x2_splat(b.y),
                    f32x2_splat(b.z), f32x2_splat(b.w)
                };
#pragma unroll
                for (int i = 0; i < 8; i++)
#pragma unroll
                    for (int j = 0; j < 4; j++)
                        acc2[i][j] = f32x2_fma(a2[i], sb[j], acc2[i][j]);
            }
        }

        // consume 256 columns in four 64-col chunks, ascending global order
        const int colbase = ct * BN;
#pragma unroll
        for (int h = 0; h < 4; h++) {
            __syncthreads();
            if ((tx >> 4) == h) {
                const int cbl = (tx & 15) << 2;
#pragma unroll
                for (int i = 0; i < 8; i++) {
                    float* rlo = sim + ((ty << 4) + (i << 1)) * SPAD + cbl;
                    float* rhi = rlo + SPAD;
#pragma unroll
                    for (int jj = 0; jj < 4; jj++) {
                        float lo, hi;
                        f32x2_unpack(acc2[i][jj], lo, hi);
                        rlo[jj] = lo;
                        rhi[jj] = hi;
                    }
                }
            }
            __syncthreads();

            if (tid < BM) {
                const int r = tid;
                const int grow = rowbase + r;
                const int cb0 = colbase + (h << 6);
                float* tvr = tv + r * TKPAD;
                int*   tir = ti + r * TKPAD;
                float thr = tvr[0];
#pragma unroll 1
                for (int c = 0; c < 64; c++) {
                    float v = sim[r * SPAD + c];
                    int j = cb0 + c;
                    if (v > thr && j != grow) {
                        int p = 0;
#pragma unroll 1
                        while (p < KTOP - 1 && tvr[p + 1] < v) {
                            tvr[p] = tvr[p + 1];
                            tir[p] = tir[p + 1];
                            p++;
                        }
                        tvr[p] = v;
                        tir[p] = j;
                        thr = tvr[0];
                    }
                }
            }
        }
    }

    __syncthreads();
    // Emit edge_index as float32 (indices < 2^24 exact):
    // out[0:N*K] = row ids, out[N*K:2*N*K] = neighbor ids, descending similarity.
    if (tid < BM) {
        const int r = tid;
        const int grow = rowbase + r;
        float* orow = out + grow * KTOP;
        float* ocol = out + NNODE * KTOP + grow * KTOP;
#pragma unroll
        for (int q = 0; q < KTOP; q++) {
            orow[q] = (float)grow;
            ocol[q] = (float)ti[r * TKPAD + (KTOP - 1 - q)];
        }
    }
}

// ---------------------------------------------------------------------------
extern "C" void kernel_launch(void* const* d_in, const int* in_sizes, int n_in,
                              void* d_out, int out_size) {
    const float* feature = (const float*)d_in[0];
    for (int i = 0; i < n_in; i++) {
        if (in_sizes[i] == NNODE * DFEAT) { feature = (const float*)d_in[i]; break; }
    }
    float* out = (float*)d_out;   // [2, 16384*16] compared as float32

    const int smem_bytes = (2 * STAGE_F + BM * SPAD + BM * TKPAD) * 4
                         + BM * TKPAD * 4;     // 107,264 B
    cudaFuncSetAttribute(simtopk_kernel,
                         cudaFuncAttributeMaxDynamicSharedMemorySize, smem_bytes);

    normalize_kernel<<<NNODE / 4, 128>>>(feature);
    simtopk_kernel<<<NNODE / BM, 256, smem_bytes>>>(out);
}